// round 5
// baseline (speedup 1.0000x reference)
#include <cuda_runtime.h>
#include <cstdint>

#define NPIXC   16384
#define PXB     8
#define THREADS 256

#define WSLICE  320        // per-pixel per-stage words (16 m * 20)
#define WSTAGE  2560       // 8 px
#define NSTG    4
#define PXS     772        // G per-pixel stride

// shared memory word offsets
#define OFF_W    0                  // 4*2560 = 10240 (W stages; overlaid by outputs at end)
#define OFF_G    10240              // 8*772 = 6176 (G chunk; overlaid by mlp_in frags)
#define OFF_W1F  16416              // 1536
#define OFF_B1   17952              // 64
#define OFF_W2F  18016              // 512
#define OFF_B2   18528              // 8
#define OFF_N    18536              // 72
#define SMEM_WORDS 18608
#define SMEM_BYTES (SMEM_WORDS * 4)   // 74432

__device__ __forceinline__ uint32_t cvt_tf32(float x) {
    uint32_t r;
    asm("cvt.rna.tf32.f32 %0, %1;" : "=r"(r) : "f"(x));
    return r;
}

__device__ __forceinline__ void mma_tf32(float* d, const uint32_t* a, uint32_t b0, uint32_t b1) {
    asm("mma.sync.aligned.m16n8k8.row.col.f32.tf32.tf32.f32 "
        "{%0,%1,%2,%3}, {%4,%5,%6,%7}, {%8,%9}, {%0,%1,%2,%3};"
        : "+f"(d[0]), "+f"(d[1]), "+f"(d[2]), "+f"(d[3])
        : "r"(a[0]), "r"(a[1]), "r"(a[2]), "r"(a[3]), "r"(b0), "r"(b1));
}

__device__ __forceinline__ int fragslot(int r, int c) {
    return ((r & 7) * 4 + (c & 3)) * 4 + (r >> 3) + 2 * ((c >> 2) & 1);
}

__device__ __forceinline__ void cp16(uint32_t dst, const void* src) {
    asm volatile("cp.async.cg.shared.global [%0], [%1], 16;" :: "r"(dst), "l"(src) : "memory");
}
__device__ __forceinline__ void cpcommit() {
    asm volatile("cp.async.commit_group;" ::: "memory");
}
template<int N> __device__ __forceinline__ void cpwait() {
    asm volatile("cp.async.wait_group %0;" :: "n"(N) : "memory");
}

__global__ void __launch_bounds__(THREADS, 3)
lr_kernel(const float* __restrict__ y,     // [16][8][NPIX]
          const float* __restrict__ nz,    // [16][8][NPIX]
          const float* __restrict__ nz2,   // [16][NPIX][8]
          const float* __restrict__ wmap,  // [NPIX][9][16][16]
          const float* __restrict__ w1,    // [64][24]
          const float* __restrict__ b1,    // [64]
          const float* __restrict__ w2,    // [8][64]
          const float* __restrict__ b2,    // [8]
          const int*   __restrict__ nidx,  // [NPIX][9]
          float*       __restrict__ out)   // [16][8][NPIX]
{
    extern __shared__ uint32_t su[];
    uint32_t* sW   = su + OFF_W;
    uint32_t* sG   = su + OFF_G;
    uint32_t* sW1f = su + OFF_W1F;
    float*    sB1f = (float*)(su + OFF_B1);
    uint32_t* sW2f = su + OFF_W2F;
    float*    sB2f = (float*)(su + OFF_B2);
    float*    sOf  = (float*)su;            // overlays W region (free after einsum)
    int*      sN   = (int*)(su + OFF_N);

    const int tid = threadIdx.x;
    const int p0  = blockIdx.x * PXB;
    const int l   = tid & 31;
    const int px  = tid >> 5;
    const int p   = p0 + px;

    // ---- W cp.async pipeline base addresses ----
    const float* wp4 = wmap + (size_t)p * 2304;
    const uint32_t wdst_px = (uint32_t)__cvta_generic_to_shared(sW) + (uint32_t)px * WSLICE * 4;

    // issue slice s (warp-private, lane l copies chunks l and l+32); ALWAYS commits
    #define W_ISSUE(s_) do {                                                         \
        int s__ = (s_);                                                              \
        if (s__ < 9) {                                                               \
            const float4* wsrc = (const float4*)(wp4 + (size_t)s__ * 256);           \
            uint32_t wd = wdst_px + (uint32_t)(s__ & 3) * WSTAGE * 4;                \
            int j0 = l, j1 = l + 32;                                                 \
            cp16(wd + (((j0 >> 2) * 20 + (j0 & 3) * 4) << 2), wsrc + j0);            \
            cp16(wd + (((j1 >> 2) * 20 + (j1 & 3) * 4) << 2), wsrc + j1);            \
        }                                                                            \
        cpcommit();                                                                  \
    } while (0)

    // prologue: get the weight stream going immediately (3 stages in flight)
    W_ISSUE(0); W_ISSUE(1); W_ISSUE(2);

    // ---- small shared weights + neighbor indices ----
    for (int i = tid; i < 1536; i += THREADS) {          // w1^T B-frags [j8][kt3][l32][rg2]
        int j = i / 192, r = i - j * 192;
        int kt = r >> 6, r2 = r & 63, ll = r2 >> 1, rg = r2 & 1;
        int d = kt * 8 + (ll & 3) + rg * 4;
        int ii = j * 8 + (ll >> 2);
        sW1f[i] = cvt_tf32(w1[ii * 24 + d]);
    }
    for (int i = tid; i < 512; i += THREADS) {           // w2^T B-frags [kt8][l32][rg2]
        int kt = i >> 6, r2 = i & 63, ll = r2 >> 1, rg = r2 & 1;
        int row = kt * 8 + (ll & 3) + 4 * rg;
        int col = ll >> 2;
        sW2f[i] = cvt_tf32(w2[col * 64 + row]);
    }
    if (tid < 64) sB1f[tid] = b1[tid];
    if (tid < 8)  sB2f[tid] = b2[tid];
    if (tid < 72) sN[tid] = nidx[p0 * 9 + tid];
    __syncthreads();

    // ---- gather geometry ----
    const int gpx = tid & 7;
    const int fo  = tid >> 3;
    const int b7  = fo & 7;
    const int nh  = fo >> 3;
    const float* gsrc = ((nh < 2) ? y : nz)
                      + (size_t)((nh & 1) * 4) * NPIXC
                      + (size_t)b7 * 8 * NPIXC;
    const int gsto = gpx * PXS + 16 * b7 + 128 * (nh >> 1);

    // ---- prologue gather: chunk 0 ----
    {
        uint32_t* dst = sG + gsto;
        #pragma unroll
        for (int kk = 0; kk < 3; ++kk) {
            int q = sN[gpx * 9 + kk];
            #pragma unroll
            for (int i = 0; i < 4; ++i) {
                const float* a = gsrc + (size_t)i * NPIXC + q;
                float lo = __ldg(a);
                float hi = __ldg(a + 64 * NPIXC);
                int off = kk * 256 + 4 * ((2 * nh + (i >> 1)) & 3) + 2 * (i & 1);
                *(uint2*)(dst + off) = make_uint2(cvt_tf32(lo), cvt_tf32(hi));
            }
        }
    }
    __syncthreads();

    // ---- main loop: 3 chunks x 3 k-slices ----
    float d0[4] = {0.f, 0.f, 0.f, 0.f};
    float d1[4] = {0.f, 0.f, 0.f, 0.f};
    const uint32_t* abase = sG + px * PXS;

    float g[24];
    #pragma unroll 1
    for (int c = 0; c < 3; ++c) {
        // prefetch next chunk's gather into registers
        if (c < 2) {
            #pragma unroll
            for (int kk = 0; kk < 3; ++kk) {
                int q = sN[gpx * 9 + (c + 1) * 3 + kk];
                #pragma unroll
                for (int i = 0; i < 4; ++i) {
                    const float* a = gsrc + (size_t)i * NPIXC + q;
                    g[kk * 8 + i * 2]     = __ldg(a);
                    g[kk * 8 + i * 2 + 1] = __ldg(a + 64 * NPIXC);
                }
            }
        }
        // 3 k-slices of MMA, weights from the cp.async pipeline
        #pragma unroll
        for (int kk = 0; kk < 3; ++kk) {
            int s = 3 * c + kk;
            W_ISSUE(s + 3);
            cpwait<3>();
            __syncwarp();
            const uint32_t* bb = sW + (uint32_t)(s & 3) * WSTAGE + px * WSLICE;
            #pragma unroll
            for (int h = 0; h < 2; ++h) {
                uint4 av = *(const uint4*)(abase + kk * 256 + h * 128 + l * 4);
                uint32_t a[4] = {av.x, av.y, av.z, av.w};
                float2 w0  = *(const float2*)(bb + (l >> 2) * 20 + 2 * (l & 3) + 8 * h);
                float2 w1v = *(const float2*)(bb + (8 + (l >> 2)) * 20 + 2 * (l & 3) + 8 * h);
                mma_tf32(d0, a, cvt_tf32(w0.x), cvt_tf32(w0.y));
                mma_tf32(d1, a, cvt_tf32(w1v.x), cvt_tf32(w1v.y));
            }
        }
        __syncthreads();
        // commit prefetched gather into the (single) G buffer
        if (c < 2) {
            uint32_t* dst = sG + gsto;
            #pragma unroll
            for (int kk = 0; kk < 3; ++kk) {
                #pragma unroll
                for (int i = 0; i < 4; ++i) {
                    int off = kk * 256 + 4 * ((2 * nh + (i >> 1)) & 3) + 2 * (i & 1);
                    *(uint2*)(dst + off) = make_uint2(cvt_tf32(g[kk * 8 + i * 2]),
                                                      cvt_tf32(g[kk * 8 + i * 2 + 1]));
                }
            }
            __syncthreads();
        }
    }

    // ---- stage mlp_in = [D1 | noise2] as A-frags (overlay G region) ----
    uint32_t* sMp = sG + px * PXS;
    {
        int r = l >> 2, cc = 2 * (l & 3);
        sMp[(cc >> 3) * 128 + fragslot(r, cc)]               = cvt_tf32(d0[0]);
        sMp[((cc + 1) >> 3) * 128 + fragslot(r, cc + 1)]     = cvt_tf32(d0[1]);
        sMp[(cc >> 3) * 128 + fragslot(r + 8, cc)]           = cvt_tf32(d0[2]);
        sMp[((cc + 1) >> 3) * 128 + fragslot(r + 8, cc + 1)] = cvt_tf32(d0[3]);
        int c8 = cc + 8;
        sMp[(c8 >> 3) * 128 + fragslot(r, c8)]               = cvt_tf32(d1[0]);
        sMp[((c8 + 1) >> 3) * 128 + fragslot(r, c8 + 1)]     = cvt_tf32(d1[1]);
        sMp[(c8 >> 3) * 128 + fragslot(r + 8, c8)]           = cvt_tf32(d1[2]);
        sMp[((c8 + 1) >> 3) * 128 + fragslot(r + 8, c8 + 1)] = cvt_tf32(d1[3]);

        int b  = l >> 1;
        int qo = (l & 1) * 4;
        float4 v = *(const float4*)(nz2 + ((size_t)b * NPIXC + p) * 8 + qo);
        sMp[2 * 128 + fragslot(b, qo + 0)] = cvt_tf32(v.x);
        sMp[2 * 128 + fragslot(b, qo + 1)] = cvt_tf32(v.y);
        sMp[2 * 128 + fragslot(b, qo + 2)] = cvt_tf32(v.z);
        sMp[2 * 128 + fragslot(b, qo + 3)] = cvt_tf32(v.w);
    }
    __syncwarp();

    // ---- GEMM2: H[16x64] = M[16x24] * w1^T[24x64] ----
    float h[8][4];
    #pragma unroll
    for (int j = 0; j < 8; ++j) { h[j][0] = h[j][1] = h[j][2] = h[j][3] = 0.f; }
    #pragma unroll
    for (int kt = 0; kt < 3; ++kt) {
        uint4 av = *(const uint4*)(sMp + kt * 128 + l * 4);
        uint32_t a[4] = {av.x, av.y, av.z, av.w};
        #pragma unroll
        for (int j = 0; j < 8; ++j) {
            uint2 bf = *(const uint2*)(sW1f + (j * 3 + kt) * 64 + l * 2);
            mma_tf32(h[j], a, bf.x, bf.y);
        }
    }

    // bias + relu in registers
    {
        int c0 = 2 * (l & 3);
        #pragma unroll
        for (int j = 0; j < 8; ++j) {
            float ba = sB1f[8 * j + c0], bb2 = sB1f[8 * j + c0 + 1];
            h[j][0] = fmaxf(h[j][0] + ba, 0.f);
            h[j][1] = fmaxf(h[j][1] + bb2, 0.f);
            h[j][2] = fmaxf(h[j][2] + ba, 0.f);
            h[j][3] = fmaxf(h[j][3] + bb2, 0.f);
        }
    }

    // ---- GEMM3 via shuffle restage: OUT[16x8] = H[16x64] * w2^T[64x8] ----
    float o[4] = {0.f, 0.f, 0.f, 0.f};
    {
        const int srcA = (l & 28) | ((l & 3) >> 1);
        const int srcB = srcA + 2;
        const bool odd = (l & 1);
        #pragma unroll
        for (int j = 0; j < 8; ++j) {
            float x0 = __shfl_sync(0xffffffffu, h[j][0], srcA);
            float x1 = __shfl_sync(0xffffffffu, h[j][1], srcA);
            float x2 = __shfl_sync(0xffffffffu, h[j][2], srcA);
            float x3 = __shfl_sync(0xffffffffu, h[j][3], srcA);
            float y0 = __shfl_sync(0xffffffffu, h[j][0], srcB);
            float y1 = __shfl_sync(0xffffffffu, h[j][1], srcB);
            float y2 = __shfl_sync(0xffffffffu, h[j][2], srcB);
            float y3 = __shfl_sync(0xffffffffu, h[j][3], srcB);
            uint32_t a[4];
            a[0] = cvt_tf32(odd ? x1 : x0);
            a[1] = cvt_tf32(odd ? x3 : x2);
            a[2] = cvt_tf32(odd ? y1 : y0);
            a[3] = cvt_tf32(odd ? y3 : y2);
            uint2 bf = *(const uint2*)(sW2f + j * 64 + l * 2);
            mma_tf32(o, a, bf.x, bf.y);
        }
    }
    {
        int f0  = 2 * (l & 3);
        int b0i = l >> 2;
        o[0] += sB2f[f0];
        o[1] += sB2f[f0 + 1];
        o[2] += sB2f[f0];
        o[3] += sB2f[f0 + 1];
        sOf[(b0i * 8 + f0) * 8 + px]           = o[0];
        sOf[(b0i * 8 + f0 + 1) * 8 + px]       = o[1];
        sOf[((b0i + 8) * 8 + f0) * 8 + px]     = o[2];
        sOf[((b0i + 8) * 8 + f0 + 1) * 8 + px] = o[3];
    }
    __syncthreads();

    // ---- coalesced output: out[bf][p0..p0+7] ----
    {
        float4 v = *(const float4*)(sOf + tid * 4);
        *(float4*)(out + (size_t)(tid >> 1) * NPIXC + p0 + (tid & 1) * 4) = v;
    }
    #undef W_ISSUE
}

extern "C" void kernel_launch(void* const* d_in, const int* in_sizes, int n_in,
                              void* d_out, int out_size)
{
    const float* y    = (const float*)d_in[0];
    const float* nz   = (const float*)d_in[1];
    const float* nz2  = (const float*)d_in[2];
    const float* wmap = (const float*)d_in[3];
    const float* w1   = (const float*)d_in[4];
    const float* b1   = (const float*)d_in[5];
    const float* w2   = (const float*)d_in[6];
    const float* b2   = (const float*)d_in[7];
    const int*   nidx = (const int*)d_in[8];
    float* out = (float*)d_out;

    cudaFuncSetAttribute(lr_kernel, cudaFuncAttributeMaxDynamicSharedMemorySize, SMEM_BYTES);
    lr_kernel<<<NPIXC / PXB, THREADS, SMEM_BYTES>>>(y, nz, nz2, wmap, w1, b1, w2, b2, nidx, out);
}

// round 7
// speedup vs baseline: 1.2853x; 1.2853x over previous
#include <cuda_runtime.h>
#include <cstdint>

#define NPIXC   16384
#define PXB     8
#define THREADS 256
#define PXS     772        // G per-pixel stride (768 + 4 pad)

// shared memory word offsets
#define OFF_G    0                  // 8*772 = 6176 (overlaid by outputs at end)
#define OFF_W1F  6176               // 1536
#define OFF_B1   7712               // 64
#define OFF_W2F  7776               // 512
#define OFF_B2   8288               // 8
#define OFF_N    8296               // 72
#define SMEM_WORDS 8368
#define SMEM_BYTES (SMEM_WORDS * 4)   // 33472 -> smem allows 4+ blocks/SM

__device__ __forceinline__ uint32_t cvt_tf32(float x) {
    uint32_t r;
    asm("cvt.rna.tf32.f32 %0, %1;" : "=r"(r) : "f"(x));
    return r;
}

__device__ __forceinline__ void mma_tf32(float* d, const uint32_t* a, uint32_t b0, uint32_t b1) {
    asm("mma.sync.aligned.m16n8k8.row.col.f32.tf32.tf32.f32 "
        "{%0,%1,%2,%3}, {%4,%5,%6,%7}, {%8,%9}, {%0,%1,%2,%3};"
        : "+f"(d[0]), "+f"(d[1]), "+f"(d[2]), "+f"(d[3])
        : "r"(a[0]), "r"(a[1]), "r"(a[2]), "r"(a[3]), "r"(b0), "r"(b1));
}

__global__ void __launch_bounds__(THREADS, 4)
lr_kernel(const float* __restrict__ y,     // [16][8][NPIX]
          const float* __restrict__ nz,    // [16][8][NPIX]
          const float* __restrict__ nz2,   // [16][NPIX][8]
          const float* __restrict__ wmap,  // [NPIX][9][16][16]
          const float* __restrict__ w1,    // [64][24]
          const float* __restrict__ b1,    // [64]
          const float* __restrict__ w2,    // [8][64]
          const float* __restrict__ b2,    // [8]
          const int*   __restrict__ nidx,  // [NPIX][9]
          float*       __restrict__ out)   // [16][8][NPIX]
{
    extern __shared__ uint32_t su[];
    uint32_t* sG   = su + OFF_G;
    uint32_t* sW1f = su + OFF_W1F;
    float*    sB1f = (float*)(su + OFF_B1);
    uint32_t* sW2f = su + OFF_W2F;
    float*    sB2f = (float*)(su + OFF_B2);
    float*    sOf  = (float*)su;            // overlays G region (freed after einsum)
    int*      sN   = (int*)(su + OFF_N);

    const int tid = threadIdx.x;
    const int p0  = blockIdx.x * PXB;
    const int l   = tid & 31;
    const int px  = tid >> 5;
    const int p   = p0 + px;

    // ---- small shared weights + neighbor indices ----
    for (int i = tid; i < 1536; i += THREADS) {          // w1^T B-frags [j8][kt3][l32][rg2]
        int j = i / 192, r = i - j * 192;
        int kt = r >> 6, r2 = r & 63, ll = r2 >> 1, rg = r2 & 1;
        int d = kt * 8 + (ll & 3) + rg * 4;
        int ii = j * 8 + (ll >> 2);
        sW1f[i] = cvt_tf32(w1[ii * 24 + d]);
    }
    for (int i = tid; i < 512; i += THREADS) {           // w2^T B-frags [kt8][l32][rg2]
        int kt = i >> 6, r2 = i & 63, ll = r2 >> 1, rg = r2 & 1;
        int row = kt * 8 + (ll & 3) + 4 * rg;
        int col = ll >> 2;
        sW2f[i] = cvt_tf32(w2[col * 64 + row]);
    }
    if (tid < 64) sB1f[tid] = b1[tid];
    if (tid < 8)  sB2f[tid] = b2[tid];
    if (tid < 72) sN[tid] = nidx[p0 * 9 + tid];

    // ---- early loads: noise2 A-fragment for GEMM2 kt=2 (hidden behind einsum) ----
    float m2a0 = __ldg(nz2 + ((size_t)(l >> 2) * NPIXC + p) * 8 + (l & 3));
    float m2a1 = __ldg(nz2 + ((size_t)((l >> 2) + 8) * NPIXC + p) * 8 + (l & 3));
    float m2a2 = __ldg(nz2 + ((size_t)(l >> 2) * NPIXC + p) * 8 + (l & 3) + 4);
    float m2a3 = __ldg(nz2 + ((size_t)((l >> 2) + 8) * NPIXC + p) * 8 + (l & 3) + 4);
    __syncthreads();

    // ---- gather geometry ----
    const int gpx = tid & 7;
    const int fo  = tid >> 3;
    const int b7  = fo & 7;
    const int nh  = fo >> 3;
    const float* gsrc = ((nh < 2) ? y : nz)
                      + (size_t)((nh & 1) * 4) * NPIXC
                      + (size_t)b7 * 8 * NPIXC;
    uint32_t* gdst = sG + gpx * PXS + 16 * b7 + 128 * (nh >> 1);

    // gather one 3-k chunk c into G (LOCAL kk offsets — buffer is reused per chunk)
    #define GATHER(c_) do {                                                          \
        int c__ = (c_);                                                              \
        _Pragma("unroll")                                                            \
        for (int kk = 0; kk < 3; ++kk) {                                             \
            int q = sN[gpx * 9 + 3 * c__ + kk];                                      \
            _Pragma("unroll")                                                        \
            for (int ih = 0; ih < 2; ++ih) {                                         \
                const float* a0p = gsrc + (size_t)(2 * ih) * NPIXC + q;              \
                const float* a1p = a0p + NPIXC;                                      \
                float lo0 = __ldg(a0p), hi0 = __ldg(a0p + 64 * NPIXC);               \
                float lo1 = __ldg(a1p), hi1 = __ldg(a1p + 64 * NPIXC);               \
                uint4 v = make_uint4(cvt_tf32(lo0), cvt_tf32(hi0),                   \
                                     cvt_tf32(lo1), cvt_tf32(hi1));                  \
                *(uint4*)(gdst + kk * 256 + 4 * ((2 * nh + ih) & 3)) = v;            \
            }                                                                        \
        }                                                                            \
    } while (0)

    GATHER(0);
    __syncthreads();

    // ---- einsum: D1[16b x 16m] = G[16x144] * W[144x16], weights gmem->regs ----
    float d0[4] = {0.f, 0.f, 0.f, 0.f};
    float d1[4] = {0.f, 0.f, 0.f, 0.f};
    const uint32_t* abase = sG + px * PXS;
    const float* wp = wmap + (size_t)p * 2304 + (l >> 2) * 16 + 2 * (l & 3);

    float2 c00, c01, c10, c11;     // current slice weights (h=0 rows m, m+8; h=1)
    #define WLOAD(s_, r00, r01, r10, r11) do {                                       \
        const float* wt = wp + (s_) * 256;                                           \
        r00 = *(const float2*)(wt);                                                  \
        r01 = *(const float2*)(wt + 128);                                            \
        r10 = *(const float2*)(wt + 8);                                              \
        r11 = *(const float2*)(wt + 136);                                            \
    } while (0)

    WLOAD(0, c00, c01, c10, c11);

    #pragma unroll 1
    for (int c = 0; c < 3; ++c) {
        #pragma unroll
        for (int kk = 0; kk < 3; ++kk) {
            int s = 3 * c + kk;
            float2 n00, n01, n10, n11;
            if (s < 8) WLOAD(s + 1, n00, n01, n10, n11);
            // h = 0
            {
                uint4 av = *(const uint4*)(abase + kk * 256 + l * 4);
                uint32_t a[4] = {av.x, av.y, av.z, av.w};
                mma_tf32(d0, a, cvt_tf32(c00.x), cvt_tf32(c00.y));
                mma_tf32(d1, a, cvt_tf32(c01.x), cvt_tf32(c01.y));
            }
            // h = 1
            {
                uint4 av = *(const uint4*)(abase + kk * 256 + 128 + l * 4);
                uint32_t a[4] = {av.x, av.y, av.z, av.w};
                mma_tf32(d0, a, cvt_tf32(c10.x), cvt_tf32(c10.y));
                mma_tf32(d1, a, cvt_tf32(c11.x), cvt_tf32(c11.y));
            }
            c00 = n00; c01 = n01; c10 = n10; c11 = n11;
        }
        if (c < 2) {
            __syncthreads();
            GATHER(c + 1);
            __syncthreads();
        }
    }
    __syncthreads();   // all G reads done; G region may be overlaid by outputs

    // ---- shuffle restage (d-frag -> A-frag permutation, validated in R5) ----
    const int srcA = (l & 28) | ((l & 3) >> 1);
    const int srcB = srcA + 2;
    const bool odd = (l & 1);

    #define RESTAGE(dd_, a_) do {                                                    \
        float x0 = __shfl_sync(0xffffffffu, (dd_)[0], srcA);                         \
        float x1 = __shfl_sync(0xffffffffu, (dd_)[1], srcA);                         \
        float x2 = __shfl_sync(0xffffffffu, (dd_)[2], srcA);                         \
        float x3 = __shfl_sync(0xffffffffu, (dd_)[3], srcA);                         \
        float y0 = __shfl_sync(0xffffffffu, (dd_)[0], srcB);                         \
        float y1 = __shfl_sync(0xffffffffu, (dd_)[1], srcB);                         \
        float y2 = __shfl_sync(0xffffffffu, (dd_)[2], srcB);                         \
        float y3 = __shfl_sync(0xffffffffu, (dd_)[3], srcB);                         \
        (a_)[0] = cvt_tf32(odd ? x1 : x0);                                           \
        (a_)[1] = cvt_tf32(odd ? x3 : x2);                                           \
        (a_)[2] = cvt_tf32(odd ? y1 : y0);                                           \
        (a_)[3] = cvt_tf32(odd ? y3 : y2);                                           \
    } while (0)

    // ---- GEMM2: H[16x64] = [D1 | noise2][16x24] * w1^T[24x64] ----
    float hh[8][4];
    #pragma unroll
    for (int j = 0; j < 8; ++j) { hh[j][0] = hh[j][1] = hh[j][2] = hh[j][3] = 0.f; }
    {
        uint32_t a[4];
        #pragma unroll
        for (int kt = 0; kt < 3; ++kt) {
            if (kt == 0)      RESTAGE(d0, a);
            else if (kt == 1) RESTAGE(d1, a);
            else {
                a[0] = cvt_tf32(m2a0); a[1] = cvt_tf32(m2a1);
                a[2] = cvt_tf32(m2a2); a[3] = cvt_tf32(m2a3);
            }
            #pragma unroll
            for (int j = 0; j < 8; ++j) {
                uint2 bf = *(const uint2*)(sW1f + (j * 3 + kt) * 64 + l * 2);
                mma_tf32(hh[j], a, bf.x, bf.y);
            }
        }
    }

    // bias + relu in registers
    {
        int c0 = 2 * (l & 3);
        #pragma unroll
        for (int j = 0; j < 8; ++j) {
            float ba = sB1f[8 * j + c0], bb2 = sB1f[8 * j + c0 + 1];
            hh[j][0] = fmaxf(hh[j][0] + ba, 0.f);
            hh[j][1] = fmaxf(hh[j][1] + bb2, 0.f);
            hh[j][2] = fmaxf(hh[j][2] + ba, 0.f);
            hh[j][3] = fmaxf(hh[j][3] + bb2, 0.f);
        }
    }

    // ---- GEMM3 via shuffle restage: OUT[16x8] = H[16x64] * w2^T[64x8] ----
    float o[4] = {0.f, 0.f, 0.f, 0.f};
    {
        uint32_t a[4];
        #pragma unroll
        for (int j = 0; j < 8; ++j) {
            RESTAGE(hh[j], a);
            uint2 bf = *(const uint2*)(sW2f + j * 64 + l * 2);
            mma_tf32(o, a, bf.x, bf.y);
        }
    }
    {
        int f0  = 2 * (l & 3);
        int b0i = l >> 2;
        o[0] += sB2f[f0];
        o[1] += sB2f[f0 + 1];
        o[2] += sB2f[f0];
        o[3] += sB2f[f0 + 1];
        sOf[(b0i * 8 + f0) * 8 + px]           = o[0];
        sOf[(b0i * 8 + f0 + 1) * 8 + px]       = o[1];
        sOf[((b0i + 8) * 8 + f0) * 8 + px]     = o[2];
        sOf[((b0i + 8) * 8 + f0 + 1) * 8 + px] = o[3];
    }
    __syncthreads();

    // ---- coalesced output: out[bf][p0..p0+7] ----
    {
        float4 v = *(const float4*)(sOf + tid * 4);
        *(float4*)(out + (size_t)(tid >> 1) * NPIXC + p0 + (tid & 1) * 4) = v;
    }
    #undef GATHER
    #undef WLOAD
    #undef RESTAGE
}

extern "C" void kernel_launch(void* const* d_in, const int* in_sizes, int n_in,
                              void* d_out, int out_size)
{
    const float* y    = (const float*)d_in[0];
    const float* nz   = (const float*)d_in[1];
    const float* nz2  = (const float*)d_in[2];
    const float* wmap = (const float*)d_in[3];
    const float* w1   = (const float*)d_in[4];
    const float* b1   = (const float*)d_in[5];
    const float* w2   = (const float*)d_in[6];
    const float* b2   = (const float*)d_in[7];
    const int*   nidx = (const int*)d_in[8];
    float* out = (float*)d_out;

    cudaFuncSetAttribute(lr_kernel, cudaFuncAttributeMaxDynamicSharedMemorySize, SMEM_BYTES);
    lr_kernel<<<NPIXC / PXB, THREADS, SMEM_BYTES>>>(y, nz, nz2, wmap, w1, b1, w2, b2, nidx, out);
}

// round 8
// speedup vs baseline: 1.3881x; 1.0799x over previous
#include <cuda_runtime.h>
#include <cstdint>

#define NPIXC   16384
#define PXB     8
#define THREADS 256

// G: two k-slice buffers, 8 px * 256 words each, XOR-swizzled (no pad)
#define KBUF    2048

// shared memory word offsets
#define OFF_G    0                  // 2*2048 = 4096 (overlaid by outputs at end)
#define OFF_W1F  4096               // 1536
#define OFF_B1   5632               // 64
#define OFF_W2F  5696               // 512
#define OFF_B2   6208               // 8
#define OFF_N    6216               // 72
#define SMEM_WORDS 6288
#define SMEM_BYTES (SMEM_WORDS * 4)   // 25152

__device__ __forceinline__ uint32_t cvt_tf32(float x) {
    uint32_t r;
    asm("cvt.rna.tf32.f32 %0, %1;" : "=r"(r) : "f"(x));
    return r;
}

__device__ __forceinline__ void mma_tf32(float* d, const uint32_t* a, uint32_t b0, uint32_t b1) {
    asm("mma.sync.aligned.m16n8k8.row.col.f32.tf32.tf32.f32 "
        "{%0,%1,%2,%3}, {%4,%5,%6,%7}, {%8,%9}, {%0,%1,%2,%3};"
        : "+f"(d[0]), "+f"(d[1]), "+f"(d[2]), "+f"(d[3])
        : "r"(a[0]), "r"(a[1]), "r"(a[2]), "r"(a[3]), "r"(b0), "r"(b1));
}

__global__ void __launch_bounds__(THREADS, 4)
lr_kernel(const float* __restrict__ y,     // [16][8][NPIX]
          const float* __restrict__ nz,    // [16][8][NPIX]
          const float* __restrict__ nz2,   // [16][NPIX][8]
          const float* __restrict__ wmap,  // [NPIX][9][16][16]
          const float* __restrict__ w1,    // [64][24]
          const float* __restrict__ b1,    // [64]
          const float* __restrict__ w2,    // [8][64]
          const float* __restrict__ b2,    // [8]
          const int*   __restrict__ nidx,  // [NPIX][9]
          float*       __restrict__ out)   // [16][8][NPIX]
{
    extern __shared__ uint32_t su[];
    uint32_t* sG   = su + OFF_G;
    uint32_t* sW1f = su + OFF_W1F;
    float*    sB1f = (float*)(su + OFF_B1);
    uint32_t* sW2f = su + OFF_W2F;
    float*    sB2f = (float*)(su + OFF_B2);
    float*    sOf  = (float*)su;            // overlays G buffers (freed after einsum)
    int*      sN   = (int*)(su + OFF_N);

    const int tid = threadIdx.x;
    const int p0  = blockIdx.x * PXB;
    const int l   = tid & 31;
    const int px  = tid >> 5;
    const int p   = p0 + px;

    // ---- small shared weights + neighbor indices ----
    for (int i = tid; i < 1536; i += THREADS) {          // w1^T B-frags [j8][kt3][l32][rg2]
        int j = i / 192, r = i - j * 192;
        int kt = r >> 6, r2 = r & 63, ll = r2 >> 1, rg = r2 & 1;
        int d = kt * 8 + (ll & 3) + rg * 4;
        int ii = j * 8 + (ll >> 2);
        sW1f[i] = cvt_tf32(w1[ii * 24 + d]);
    }
    for (int i = tid; i < 512; i += THREADS) {           // w2^T B-frags [kt8][l32][rg2]
        int kt = i >> 6, r2 = i & 63, ll = r2 >> 1, rg = r2 & 1;
        int row = kt * 8 + (ll & 3) + 4 * rg;
        int col = ll >> 2;
        sW2f[i] = cvt_tf32(w2[col * 64 + row]);
    }
    if (tid < 64) sB1f[tid] = b1[tid];
    if (tid < 8)  sB2f[tid] = b2[tid];
    if (tid < 72) sN[tid] = nidx[p0 * 9 + tid];

    // ---- early loads: noise2 A-fragment for GEMM2 kt=2 ----
    float m2a0 = __ldg(nz2 + ((size_t)(l >> 2) * NPIXC + p) * 8 + (l & 3));
    float m2a1 = __ldg(nz2 + ((size_t)((l >> 2) + 8) * NPIXC + p) * 8 + (l & 3));
    float m2a2 = __ldg(nz2 + ((size_t)(l >> 2) * NPIXC + p) * 8 + (l & 3) + 4);
    float m2a3 = __ldg(nz2 + ((size_t)((l >> 2) + 8) * NPIXC + p) * 8 + (l & 3) + 4);
    __syncthreads();

    // ---- gather geometry (cross-warp roles; px fastest for coalescing) ----
    const int gpx = tid & 7;
    const int fo  = tid >> 3;
    const int b7  = fo & 7;
    const int nh  = fo >> 3;
    const float* gsrc = ((nh < 2) ? y : nz)
                      + (size_t)((nh & 1) * 4) * NPIXC
                      + (size_t)b7 * 8 * NPIXC;
    const int gxr   = gpx << 2;                               // STS swizzle
    const int gbase = gpx * 256;                              // within a k-buffer
    const int go0   = 16 * b7 + 128 * (nh >> 1);

    // ---- prologue: gather slice 0 straight into buffer 0 ----
    {
        int q = sN[gpx * 9 + 0];
        #pragma unroll
        for (int ih = 0; ih < 2; ++ih) {
            const float* a0p = gsrc + (size_t)(2 * ih) * NPIXC + q;
            float lo0 = __ldg(a0p),          hi0 = __ldg(a0p + 64 * NPIXC);
            float lo1 = __ldg(a0p + NPIXC),  hi1 = __ldg(a0p + NPIXC + 64 * NPIXC);
            int o = (go0 + 4 * ((2 * nh + ih) & 3)) ^ gxr;
            *(uint4*)(sG + gbase + o) = make_uint4(cvt_tf32(lo0), cvt_tf32(hi0),
                                                   cvt_tf32(lo1), cvt_tf32(hi1));
        }
    }

    // ---- einsum weight pointer + first slice weights ----
    const float* wp = wmap + (size_t)p * 2304 + (l >> 2) * 16 + 2 * (l & 3);
    float2 c00, c01, c10, c11;
    #define WLOAD(s_, r00, r01, r10, r11) do {                                       \
        const float* wt = wp + (s_) * 256;                                           \
        r00 = *(const float2*)(wt);                                                  \
        r01 = *(const float2*)(wt + 128);                                            \
        r10 = *(const float2*)(wt + 8);                                              \
        r11 = *(const float2*)(wt + 136);                                            \
    } while (0)
    WLOAD(0, c00, c01, c10, c11);
    __syncthreads();

    // ---- main pipeline: 9 stages, double-buffered k-slices ----
    float d0[4] = {0.f, 0.f, 0.f, 0.f};
    float d1[4] = {0.f, 0.f, 0.f, 0.f};
    const int lxr = (px << 2);                                // LDS swizzle

    #pragma unroll 1
    for (int k = 0; k < 9; ++k) {
        // 1) prefetch next slice: gather -> regs, W -> regs
        float gr[8];
        float2 n00, n01, n10, n11;
        if (k < 8) {
            int q = sN[gpx * 9 + k + 1];
            #pragma unroll
            for (int ih = 0; ih < 2; ++ih) {
                const float* a0p = gsrc + (size_t)(2 * ih) * NPIXC + q;
                gr[ih * 4 + 0] = __ldg(a0p);
                gr[ih * 4 + 1] = __ldg(a0p + 64 * NPIXC);
                gr[ih * 4 + 2] = __ldg(a0p + NPIXC);
                gr[ih * 4 + 3] = __ldg(a0p + NPIXC + 64 * NPIXC);
            }
            WLOAD(k + 1, n00, n01, n10, n11);
        }
        // 2) MMAs for slice k from buffer k&1
        {
            const uint32_t* kb = sG + (k & 1) * KBUF + px * 256;
            uint4 av0 = *(const uint4*)(kb + ((l * 4) ^ lxr));
            uint32_t a0[4] = {av0.x, av0.y, av0.z, av0.w};
            mma_tf32(d0, a0, cvt_tf32(c00.x), cvt_tf32(c00.y));
            mma_tf32(d1, a0, cvt_tf32(c01.x), cvt_tf32(c01.y));
            uint4 av1 = *(const uint4*)(kb + ((128 + l * 4) ^ lxr));
            uint32_t a1[4] = {av1.x, av1.y, av1.z, av1.w};
            mma_tf32(d0, a1, cvt_tf32(c10.x), cvt_tf32(c10.y));
            mma_tf32(d1, a1, cvt_tf32(c11.x), cvt_tf32(c11.y));
        }
        // 3) commit prefetched gather into the other buffer
        if (k < 8) {
            uint32_t* wb = sG + ((k + 1) & 1) * KBUF + gbase;
            #pragma unroll
            for (int ih = 0; ih < 2; ++ih) {
                int o = (go0 + 4 * ((2 * nh + ih) & 3)) ^ gxr;
                *(uint4*)(wb + o) = make_uint4(cvt_tf32(gr[ih * 4 + 0]), cvt_tf32(gr[ih * 4 + 1]),
                                               cvt_tf32(gr[ih * 4 + 2]), cvt_tf32(gr[ih * 4 + 3]));
            }
            c00 = n00; c01 = n01; c10 = n10; c11 = n11;
        }
        // 4) stage boundary
        __syncthreads();
    }

    // ---- shuffle restage (d-frag -> A-frag permutation, validated R5/R7) ----
    const int srcA = (l & 28) | ((l & 3) >> 1);
    const int srcB = srcA + 2;
    const bool odd = (l & 1);

    #define RESTAGE(dd_, a_) do {                                                    \
        float x0 = __shfl_sync(0xffffffffu, (dd_)[0], srcA);                         \
        float x1 = __shfl_sync(0xffffffffu, (dd_)[1], srcA);                         \
        float x2 = __shfl_sync(0xffffffffu, (dd_)[2], srcA);                         \
        float x3 = __shfl_sync(0xffffffffu, (dd_)[3], srcA);                         \
        float y0 = __shfl_sync(0xffffffffu, (dd_)[0], srcB);                         \
        float y1 = __shfl_sync(0xffffffffu, (dd_)[1], srcB);                         \
        float y2 = __shfl_sync(0xffffffffu, (dd_)[2], srcB);                         \
        float y3 = __shfl_sync(0xffffffffu, (dd_)[3], srcB);                         \
        (a_)[0] = cvt_tf32(odd ? x1 : x0);                                           \
        (a_)[1] = cvt_tf32(odd ? x3 : x2);                                           \
        (a_)[2] = cvt_tf32(odd ? y1 : y0);                                           \
        (a_)[3] = cvt_tf32(odd ? y3 : y2);                                           \
    } while (0)

    // ---- GEMM2: H[16x64] = [D1 | noise2][16x24] * w1^T[24x64] ----
    float hh[8][4];
    #pragma unroll
    for (int j = 0; j < 8; ++j) { hh[j][0] = hh[j][1] = hh[j][2] = hh[j][3] = 0.f; }
    {
        uint32_t a[4];
        #pragma unroll
        for (int kt = 0; kt < 3; ++kt) {
            if (kt == 0)      RESTAGE(d0, a);
            else if (kt == 1) RESTAGE(d1, a);
            else {
                a[0] = cvt_tf32(m2a0); a[1] = cvt_tf32(m2a1);
                a[2] = cvt_tf32(m2a2); a[3] = cvt_tf32(m2a3);
            }
            #pragma unroll
            for (int j = 0; j < 8; ++j) {
                uint2 bf = *(const uint2*)(sW1f + (j * 3 + kt) * 64 + l * 2);
                mma_tf32(hh[j], a, bf.x, bf.y);
            }
        }
    }

    // bias + relu in registers
    {
        int c0 = 2 * (l & 3);
        #pragma unroll
        for (int j = 0; j < 8; ++j) {
            float ba = sB1f[8 * j + c0], bb2 = sB1f[8 * j + c0 + 1];
            hh[j][0] = fmaxf(hh[j][0] + ba, 0.f);
            hh[j][1] = fmaxf(hh[j][1] + bb2, 0.f);
            hh[j][2] = fmaxf(hh[j][2] + ba, 0.f);
            hh[j][3] = fmaxf(hh[j][3] + bb2, 0.f);
        }
    }

    // ---- GEMM3: OUT[16x8] = H[16x64] * w2^T[64x8] ----
    float o[4] = {0.f, 0.f, 0.f, 0.f};
    {
        uint32_t a[4];
        #pragma unroll
        for (int j = 0; j < 8; ++j) {
            RESTAGE(hh[j], a);
            uint2 bf = *(const uint2*)(sW2f + j * 64 + l * 2);
            mma_tf32(o, a, bf.x, bf.y);
        }
    }
    {
        int f0  = 2 * (l & 3);
        int b0i = l >> 2;
        o[0] += sB2f[f0];
        o[1] += sB2f[f0 + 1];
        o[2] += sB2f[f0];
        o[3] += sB2f[f0 + 1];
        sOf[(b0i * 8 + f0) * 8 + px]           = o[0];
        sOf[(b0i * 8 + f0 + 1) * 8 + px]       = o[1];
        sOf[((b0i + 8) * 8 + f0) * 8 + px]     = o[2];
        sOf[((b0i + 8) * 8 + f0 + 1) * 8 + px] = o[3];
    }
    __syncthreads();

    // ---- coalesced output: out[bf][p0..p0+7] ----
    {
        float4 v = *(const float4*)(sOf + tid * 4);
        *(float4*)(out + (size_t)(tid >> 1) * NPIXC + p0 + (tid & 1) * 4) = v;
    }
    #undef WLOAD
    #undef RESTAGE
}

extern "C" void kernel_launch(void* const* d_in, const int* in_sizes, int n_in,
                              void* d_out, int out_size)
{
    const float* y    = (const float*)d_in[0];
    const float* nz   = (const float*)d_in[1];
    const float* nz2  = (const float*)d_in[2];
    const float* wmap = (const float*)d_in[3];
    const float* w1   = (const float*)d_in[4];
    const float* b1   = (const float*)d_in[5];
    const float* w2   = (const float*)d_in[6];
    const float* b2   = (const float*)d_in[7];
    const int*   nidx = (const int*)d_in[8];
    float* out = (float*)d_out;

    cudaFuncSetAttribute(lr_kernel, cudaFuncAttributeMaxDynamicSharedMemorySize, SMEM_BYTES);
    lr_kernel<<<NPIXC / PXB, THREADS, SMEM_BYTES>>>(y, nz, nz2, wmap, w1, b1, w2, b2, nidx, out);
}

// round 9
// speedup vs baseline: 1.4288x; 1.0294x over previous
#include <cuda_runtime.h>
#include <cstdint>

#define NPIXC   16384
#define PXB     32
#define THREADS 1024
#define KBUF    8192       // one k-slice buffer: 32 px * 256 words

// shared memory word offsets
#define OFF_G    0                  // 2*8192 = 16384 (overlaid by outputs at end)
#define OFF_W1F  16384              // 1536
#define OFF_B1   17920              // 64
#define OFF_W2F  17984              // 512
#define OFF_B2   18496              // 8
#define OFF_N    18504              // 288 ints
#define SMEM_WORDS 18792
#define SMEM_BYTES (SMEM_WORDS * 4)   // 75168

__device__ __forceinline__ uint32_t cvt_tf32(float x) {
    uint32_t r;
    asm("cvt.rna.tf32.f32 %0, %1;" : "=r"(r) : "f"(x));
    return r;
}

__device__ __forceinline__ void mma_tf32(float* d, const uint32_t* a, uint32_t b0, uint32_t b1) {
    asm("mma.sync.aligned.m16n8k8.row.col.f32.tf32.tf32.f32 "
        "{%0,%1,%2,%3}, {%4,%5,%6,%7}, {%8,%9}, {%0,%1,%2,%3};"
        : "+f"(d[0]), "+f"(d[1]), "+f"(d[2]), "+f"(d[3])
        : "r"(a[0]), "r"(a[1]), "r"(a[2]), "r"(a[3]), "r"(b0), "r"(b1));
}

__global__ void __launch_bounds__(THREADS, 1)
lr_kernel(const float* __restrict__ y,     // [16][8][NPIX]
          const float* __restrict__ nz,    // [16][8][NPIX]
          const float* __restrict__ nz2,   // [16][NPIX][8]
          const float* __restrict__ wmap,  // [NPIX][9][16][16]
          const float* __restrict__ w1,    // [64][24]
          const float* __restrict__ b1,    // [64]
          const float* __restrict__ w2,    // [8][64]
          const float* __restrict__ b2,    // [8]
          const int*   __restrict__ nidx,  // [NPIX][9]
          float*       __restrict__ out)   // [16][8][NPIX]
{
    extern __shared__ uint32_t su[];
    uint32_t* sG   = su + OFF_G;
    uint32_t* sW1f = su + OFF_W1F;
    float*    sB1f = (float*)(su + OFF_B1);
    uint32_t* sW2f = su + OFF_W2F;
    float*    sB2f = (float*)(su + OFF_B2);
    float*    sOf  = (float*)su;            // overlays G buffers (freed after einsum); stride 33
    int*      sN   = (int*)(su + OFF_N);

    const int tid = threadIdx.x;
    const int p0  = blockIdx.x * PXB;
    const int l   = tid & 31;
    const int wid = tid >> 5;               // warp id == pixel for einsum/tail
    const int p   = p0 + wid;

    // ---- small shared weights + neighbor indices ----
    for (int i = tid; i < 1536; i += THREADS) {          // w1^T B-frags [j8][kt3][l32][rg2]
        int j = i / 192, r = i - j * 192;
        int kt = r >> 6, r2 = r & 63, ll = r2 >> 1, rg = r2 & 1;
        int d = kt * 8 + (ll & 3) + rg * 4;
        int ii = j * 8 + (ll >> 2);
        sW1f[i] = cvt_tf32(w1[ii * 24 + d]);
    }
    if (tid < 512) {                                     // w2^T B-frags [kt8][l32][rg2]
        int i = tid;
        int kt = i >> 6, r2 = i & 63, ll = r2 >> 1, rg = r2 & 1;
        int row = kt * 8 + (ll & 3) + 4 * rg;
        int col = ll >> 2;
        sW2f[i] = cvt_tf32(w2[col * 64 + row]);
    }
    if (tid < 64)  sB1f[tid] = b1[tid];
    if (tid < 8)   sB2f[tid] = b2[tid];
    if (tid < 288) sN[tid] = nidx[p0 * 9 + tid];

    // ---- early loads: noise2 A-fragment for GEMM2 kt=2 ----
    float m2a0 = __ldg(nz2 + ((size_t)(l >> 2) * NPIXC + p) * 8 + (l & 3));
    float m2a1 = __ldg(nz2 + ((size_t)((l >> 2) + 8) * NPIXC + p) * 8 + (l & 3));
    float m2a2 = __ldg(nz2 + ((size_t)(l >> 2) * NPIXC + p) * 8 + (l & 3) + 4);
    float m2a3 = __ldg(nz2 + ((size_t)((l >> 2) + 8) * NPIXC + p) * 8 + (l & 3) + 4);
    __syncthreads();

    // ---- gather geometry: warp = (b7,nh) role; LANES = 32 pixels (coalesced!) ----
    const int b7 = wid & 7;
    const int nh = wid >> 3;
    const float* gsrc = ((nh < 2) ? y : nz)
                      + (size_t)((nh & 1) * 4) * NPIXC
                      + (size_t)b7 * 8 * NPIXC;
    const int gxr   = (l & 7) << 2;                      // store swizzle (px = lane)
    const int gbase = l * 256;                           // px region within a k-buffer
    const int go0   = 16 * b7 + 128 * (nh >> 1);

    // ---- prologue: gather slice 0 into buffer 0 ----
    {
        int q = sN[l * 9 + 0];
        #pragma unroll
        for (int ih = 0; ih < 2; ++ih) {
            const float* a0p = gsrc + (size_t)(2 * ih) * NPIXC + q;
            float lo0 = __ldg(a0p),          hi0 = __ldg(a0p + 64 * NPIXC);
            float lo1 = __ldg(a0p + NPIXC),  hi1 = __ldg(a0p + NPIXC + 64 * NPIXC);
            int o = (go0 + 4 * ((2 * nh + ih) & 3)) ^ gxr;
            *(uint4*)(sG + gbase + o) = make_uint4(cvt_tf32(lo0), cvt_tf32(hi0),
                                                   cvt_tf32(lo1), cvt_tf32(hi1));
        }
    }

    // ---- einsum weight pointer + first slice weights ----
    const float* wp = wmap + (size_t)p * 2304 + (l >> 2) * 16 + 2 * (l & 3);
    float2 c00, c01, c10, c11;
    #define WLOAD(s_, r00, r01, r10, r11) do {                                       \
        const float* wt = wp + (s_) * 256;                                           \
        r00 = *(const float2*)(wt);                                                  \
        r01 = *(const float2*)(wt + 128);                                            \
        r10 = *(const float2*)(wt + 8);                                              \
        r11 = *(const float2*)(wt + 136);                                            \
    } while (0)
    WLOAD(0, c00, c01, c10, c11);
    __syncthreads();

    // ---- main pipeline: 9 stages, double-buffered k-slices ----
    float d0[4] = {0.f, 0.f, 0.f, 0.f};
    float d1[4] = {0.f, 0.f, 0.f, 0.f};
    const int lxr = (wid & 7) << 2;                      // read swizzle (px = wid)

    #pragma unroll 1
    for (int k = 0; k < 9; ++k) {
        // 1) prefetch next slice: gather -> regs, W -> regs
        float gr[8];
        float2 n00, n01, n10, n11;
        if (k < 8) {
            int q = sN[l * 9 + k + 1];
            #pragma unroll
            for (int ih = 0; ih < 2; ++ih) {
                const float* a0p = gsrc + (size_t)(2 * ih) * NPIXC + q;
                gr[ih * 4 + 0] = __ldg(a0p);
                gr[ih * 4 + 1] = __ldg(a0p + 64 * NPIXC);
                gr[ih * 4 + 2] = __ldg(a0p + NPIXC);
                gr[ih * 4 + 3] = __ldg(a0p + NPIXC + 64 * NPIXC);
            }
            WLOAD(k + 1, n00, n01, n10, n11);
        }
        // 2) MMAs for slice k from buffer k&1
        {
            const uint32_t* kb = sG + (k & 1) * KBUF + wid * 256;
            uint4 av0 = *(const uint4*)(kb + ((l * 4) ^ lxr));
            uint32_t a0[4] = {av0.x, av0.y, av0.z, av0.w};
            mma_tf32(d0, a0, cvt_tf32(c00.x), cvt_tf32(c00.y));
            mma_tf32(d1, a0, cvt_tf32(c01.x), cvt_tf32(c01.y));
            uint4 av1 = *(const uint4*)(kb + ((128 + l * 4) ^ lxr));
            uint32_t a1[4] = {av1.x, av1.y, av1.z, av1.w};
            mma_tf32(d0, a1, cvt_tf32(c10.x), cvt_tf32(c10.y));
            mma_tf32(d1, a1, cvt_tf32(c11.x), cvt_tf32(c11.y));
        }
        // 3) commit prefetched gather into the other buffer
        if (k < 8) {
            uint32_t* wb = sG + ((k + 1) & 1) * KBUF + gbase;
            #pragma unroll
            for (int ih = 0; ih < 2; ++ih) {
                int o = (go0 + 4 * ((2 * nh + ih) & 3)) ^ gxr;
                *(uint4*)(wb + o) = make_uint4(cvt_tf32(gr[ih * 4 + 0]), cvt_tf32(gr[ih * 4 + 1]),
                                               cvt_tf32(gr[ih * 4 + 2]), cvt_tf32(gr[ih * 4 + 3]));
            }
            c00 = n00; c01 = n01; c10 = n10; c11 = n11;
        }
        // 4) stage boundary
        __syncthreads();
    }

    // ---- shuffle restage (d-frag -> A-frag permutation, validated R5/R7/R8) ----
    const int srcA = (l & 28) | ((l & 3) >> 1);
    const int srcB = srcA + 2;
    const bool odd = (l & 1);

    #define RESTAGE(dd_, a_) do {                                                    \
        float x0 = __shfl_sync(0xffffffffu, (dd_)[0], srcA);                         \
        float x1 = __shfl_sync(0xffffffffu, (dd_)[1], srcA);                         \
        float x2 = __shfl_sync(0xffffffffu, (dd_)[2], srcA);                         \
        float x3 = __shfl_sync(0xffffffffu, (dd_)[3], srcA);                         \
        float y0 = __shfl_sync(0xffffffffu, (dd_)[0], srcB);                         \
        float y1 = __shfl_sync(0xffffffffu, (dd_)[1], srcB);                         \
        float y2 = __shfl_sync(0xffffffffu, (dd_)[2], srcB);                         \
        float y3 = __shfl_sync(0xffffffffu, (dd_)[3], srcB);                         \
        (a_)[0] = cvt_tf32(odd ? x1 : x0);                                           \
        (a_)[1] = cvt_tf32(odd ? x3 : x2);                                           \
        (a_)[2] = cvt_tf32(odd ? y1 : y0);                                           \
        (a_)[3] = cvt_tf32(odd ? y3 : y2);                                           \
    } while (0)

    // ---- GEMM2: H[16x64] = [D1 | noise2][16x24] * w1^T[24x64] ----
    float hh[8][4];
    #pragma unroll
    for (int j = 0; j < 8; ++j) { hh[j][0] = hh[j][1] = hh[j][2] = hh[j][3] = 0.f; }
    {
        uint32_t a[4];
        #pragma unroll
        for (int kt = 0; kt < 3; ++kt) {
            if (kt == 0)      RESTAGE(d0, a);
            else if (kt == 1) RESTAGE(d1, a);
            else {
                a[0] = cvt_tf32(m2a0); a[1] = cvt_tf32(m2a1);
                a[2] = cvt_tf32(m2a2); a[3] = cvt_tf32(m2a3);
            }
            #pragma unroll
            for (int j = 0; j < 8; ++j) {
                uint2 bf = *(const uint2*)(sW1f + (j * 3 + kt) * 64 + l * 2);
                mma_tf32(hh[j], a, bf.x, bf.y);
            }
        }
    }

    // bias + relu in registers
    {
        int c0 = 2 * (l & 3);
        #pragma unroll
        for (int j = 0; j < 8; ++j) {
            float ba = sB1f[8 * j + c0], bb2 = sB1f[8 * j + c0 + 1];
            hh[j][0] = fmaxf(hh[j][0] + ba, 0.f);
            hh[j][1] = fmaxf(hh[j][1] + bb2, 0.f);
            hh[j][2] = fmaxf(hh[j][2] + ba, 0.f);
            hh[j][3] = fmaxf(hh[j][3] + bb2, 0.f);
        }
    }

    // ---- GEMM3: OUT[16x8] = H[16x64] * w2^T[64x8] ----
    float o[4] = {0.f, 0.f, 0.f, 0.f};
    {
        uint32_t a[4];
        #pragma unroll
        for (int j = 0; j < 8; ++j) {
            RESTAGE(hh[j], a);
            uint2 bf = *(const uint2*)(sW2f + j * 64 + l * 2);
            mma_tf32(o, a, bf.x, bf.y);
        }
    }
    {
        int f0  = 2 * (l & 3);
        int b0i = l >> 2;
        o[0] += sB2f[f0];
        o[1] += sB2f[f0 + 1];
        o[2] += sB2f[f0];
        o[3] += sB2f[f0 + 1];
        // stage to sOf[row][px], row stride 33 (2-way conflicts at most)
        sOf[(b0i * 8 + f0) * 33 + wid]           = o[0];
        sOf[(b0i * 8 + f0 + 1) * 33 + wid]       = o[1];
        sOf[((b0i + 8) * 8 + f0) * 33 + wid]     = o[2];
        sOf[((b0i + 8) * 8 + f0 + 1) * 33 + wid] = o[3];
    }
    __syncthreads();

    // ---- coalesced output: out[bf][p0..p0+31] ----
    {
        int bf = tid >> 3;
        int c  = tid & 7;
        const float* rp = sOf + bf * 33 + c * 4;
        float4 v = make_float4(rp[0], rp[1], rp[2], rp[3]);
        *(float4*)(out + (size_t)bf * NPIXC + p0 + c * 4) = v;
    }
    #undef WLOAD
    #undef RESTAGE
}

extern "C" void kernel_launch(void* const* d_in, const int* in_sizes, int n_in,
                              void* d_out, int out_size)
{
    const float* y    = (const float*)d_in[0];
    const float* nz   = (const float*)d_in[1];
    const float* nz2  = (const float*)d_in[2];
    const float* wmap = (const float*)d_in[3];
    const float* w1   = (const float*)d_in[4];
    const float* b1   = (const float*)d_in[5];
    const float* w2   = (const float*)d_in[6];
    const float* b2   = (const float*)d_in[7];
    const int*   nidx = (const int*)d_in[8];
    float* out = (float*)d_out;

    cudaFuncSetAttribute(lr_kernel, cudaFuncAttributeMaxDynamicSharedMemorySize, SMEM_BYTES);
    lr_kernel<<<NPIXC / PXB, THREADS, SMEM_BYTES>>>(y, nz, nz2, wmap, w1, b1, w2, b2, nidx, out);
}

// round 10
// speedup vs baseline: 1.5194x; 1.0634x over previous
#include <cuda_runtime.h>
#include <cstdint>

#define NPIXC   16384
#define PXB     16
#define THREADS 512
#define KBUF    4096       // one k-slice buffer: 16 px * 256 words

// shared memory word offsets
#define OFF_G    0                  // 2*4096 = 8192 (overlaid by outputs at end)
#define OFF_W1F  8192               // 1536
#define OFF_B1   9728               // 64
#define OFF_W2F  9792               // 512
#define OFF_B2   10304              // 8
#define OFF_N    10312              // 144 ints
#define SMEM_WORDS 10456
#define SMEM_BYTES (SMEM_WORDS * 4)   // 41824 -> 2 blocks/SM

__device__ __forceinline__ uint32_t cvt_tf32(float x) {
    uint32_t r;
    asm("cvt.rna.tf32.f32 %0, %1;" : "=r"(r) : "f"(x));
    return r;
}

__device__ __forceinline__ void mma_tf32(float* d, const uint32_t* a, uint32_t b0, uint32_t b1) {
    asm("mma.sync.aligned.m16n8k8.row.col.f32.tf32.tf32.f32 "
        "{%0,%1,%2,%3}, {%4,%5,%6,%7}, {%8,%9}, {%0,%1,%2,%3};"
        : "+f"(d[0]), "+f"(d[1]), "+f"(d[2]), "+f"(d[3])
        : "r"(a[0]), "r"(a[1]), "r"(a[2]), "r"(a[3]), "r"(b0), "r"(b1));
}

__global__ void __launch_bounds__(THREADS, 2)
lr_kernel(const float* __restrict__ y,     // [16][8][NPIX]
          const float* __restrict__ nz,    // [16][8][NPIX]
          const float* __restrict__ nz2,   // [16][NPIX][8]
          const float* __restrict__ wmap,  // [NPIX][9][16][16]
          const float* __restrict__ w1,    // [64][24]
          const float* __restrict__ b1,    // [64]
          const float* __restrict__ w2,    // [8][64]
          const float* __restrict__ b2,    // [8]
          const int*   __restrict__ nidx,  // [NPIX][9]
          float*       __restrict__ out)   // [16][8][NPIX]
{
    extern __shared__ uint32_t su[];
    uint32_t* sG   = su + OFF_G;
    uint32_t* sW1f = su + OFF_W1F;
    float*    sB1f = (float*)(su + OFF_B1);
    uint32_t* sW2f = su + OFF_W2F;
    float*    sB2f = (float*)(su + OFF_B2);
    float*    sOf  = (float*)su;            // overlays G buffers (freed after einsum); stride 17
    int*      sN   = (int*)(su + OFF_N);

    const int tid = threadIdx.x;
    const int p0  = blockIdx.x * PXB;
    const int l   = tid & 31;
    const int wid = tid >> 5;               // warp id == pixel for einsum/tail
    const int p   = p0 + wid;

    // ---- small shared weights + neighbor indices ----
    for (int i = tid; i < 1536; i += THREADS) {          // w1^T B-frags [j8][kt3][l32][rg2]
        int j = i / 192, r = i - j * 192;
        int kt = r >> 6, r2 = r & 63, ll = r2 >> 1, rg = r2 & 1;
        int d = kt * 8 + (ll & 3) + rg * 4;
        int ii = j * 8 + (ll >> 2);
        sW1f[i] = cvt_tf32(w1[ii * 24 + d]);
    }
    if (tid < 512) {                                     // w2^T B-frags [kt8][l32][rg2]
        int i = tid;
        int kt = i >> 6, r2 = i & 63, ll = r2 >> 1, rg = r2 & 1;
        int row = kt * 8 + (ll & 3) + 4 * rg;
        int col = ll >> 2;
        sW2f[i] = cvt_tf32(w2[col * 64 + row]);
    }
    if (tid < 64)  sB1f[tid] = b1[tid];
    if (tid < 8)   sB2f[tid] = b2[tid];
    if (tid < 144) sN[tid] = nidx[p0 * 9 + tid];

    // ---- early loads: noise2 A-fragment for GEMM2 kt=2 ----
    float m2a0 = __ldg(nz2 + ((size_t)(l >> 2) * NPIXC + p) * 8 + (l & 3));
    float m2a1 = __ldg(nz2 + ((size_t)((l >> 2) + 8) * NPIXC + p) * 8 + (l & 3));
    float m2a2 = __ldg(nz2 + ((size_t)(l >> 2) * NPIXC + p) * 8 + (l & 3) + 4);
    float m2a3 = __ldg(nz2 + ((size_t)((l >> 2) + 8) * NPIXC + p) * 8 + (l & 3) + 4);
    __syncthreads();

    // ---- gather geometry: thread role = (px16, b7, nh); 16 consecutive px per LDG ----
    const int gpx = tid & 15;
    const int fo  = tid >> 4;            // 0..31
    const int b7  = fo & 7;
    const int nh  = fo >> 3;
    const float* gsrc = ((nh < 2) ? y : nz)
                      + (size_t)((nh & 1) * 4) * NPIXC
                      + (size_t)b7 * 8 * NPIXC;
    const int gxr   = (gpx & 7) << 2;                    // store swizzle
    const int gbase = gpx * 256;                         // px region within a k-buffer
    const int go0   = 16 * b7 + 128 * (nh >> 1);

    // ---- prologue: gather slice 0 into buffer 0 ----
    {
        int q = sN[gpx * 9 + 0];
        #pragma unroll
        for (int ih = 0; ih < 2; ++ih) {
            const float* a0p = gsrc + (size_t)(2 * ih) * NPIXC + q;
            float lo0 = __ldg(a0p),          hi0 = __ldg(a0p + 64 * NPIXC);
            float lo1 = __ldg(a0p + NPIXC),  hi1 = __ldg(a0p + NPIXC + 64 * NPIXC);
            int o = (go0 + 4 * ((2 * nh + ih) & 3)) ^ gxr;
            *(uint4*)(sG + gbase + o) = make_uint4(cvt_tf32(lo0), cvt_tf32(hi0),
                                                   cvt_tf32(lo1), cvt_tf32(hi1));
        }
    }

    // ---- einsum weight pointer + first slice weights ----
    const float* wp = wmap + (size_t)p * 2304 + (l >> 2) * 16 + 2 * (l & 3);
    float2 c00, c01, c10, c11;
    #define WLOAD(s_, r00, r01, r10, r11) do {                                       \
        const float* wt = wp + (s_) * 256;                                           \
        r00 = *(const float2*)(wt);                                                  \
        r01 = *(const float2*)(wt + 128);                                            \
        r10 = *(const float2*)(wt + 8);                                              \
        r11 = *(const float2*)(wt + 136);                                            \
    } while (0)
    WLOAD(0, c00, c01, c10, c11);
    __syncthreads();

    // ---- main pipeline: 9 stages, double-buffered k-slices ----
    float d0[4] = {0.f, 0.f, 0.f, 0.f};
    float d1[4] = {0.f, 0.f, 0.f, 0.f};
    const int lxr = (wid & 7) << 2;                      // read swizzle (px = wid)

    #pragma unroll 1
    for (int k = 0; k < 9; ++k) {
        // 1) prefetch next slice: gather -> regs, W -> regs
        float gr[8];
        float2 n00, n01, n10, n11;
        if (k < 8) {
            int q = sN[gpx * 9 + k + 1];
            #pragma unroll
            for (int ih = 0; ih < 2; ++ih) {
                const float* a0p = gsrc + (size_t)(2 * ih) * NPIXC + q;
                gr[ih * 4 + 0] = __ldg(a0p);
                gr[ih * 4 + 1] = __ldg(a0p + 64 * NPIXC);
                gr[ih * 4 + 2] = __ldg(a0p + NPIXC);
                gr[ih * 4 + 3] = __ldg(a0p + NPIXC + 64 * NPIXC);
            }
            WLOAD(k + 1, n00, n01, n10, n11);
        }
        // 2) MMAs for slice k from buffer k&1
        {
            const uint32_t* kb = sG + (k & 1) * KBUF + wid * 256;
            uint4 av0 = *(const uint4*)(kb + ((l * 4) ^ lxr));
            uint32_t a0[4] = {av0.x, av0.y, av0.z, av0.w};
            mma_tf32(d0, a0, cvt_tf32(c00.x), cvt_tf32(c00.y));
            mma_tf32(d1, a0, cvt_tf32(c01.x), cvt_tf32(c01.y));
            uint4 av1 = *(const uint4*)(kb + ((128 + l * 4) ^ lxr));
            uint32_t a1[4] = {av1.x, av1.y, av1.z, av1.w};
            mma_tf32(d0, a1, cvt_tf32(c10.x), cvt_tf32(c10.y));
            mma_tf32(d1, a1, cvt_tf32(c11.x), cvt_tf32(c11.y));
        }
        // 3) commit prefetched gather into the other buffer
        if (k < 8) {
            uint32_t* wb = sG + ((k + 1) & 1) * KBUF + gbase;
            #pragma unroll
            for (int ih = 0; ih < 2; ++ih) {
                int o = (go0 + 4 * ((2 * nh + ih) & 3)) ^ gxr;
                *(uint4*)(wb + o) = make_uint4(cvt_tf32(gr[ih * 4 + 0]), cvt_tf32(gr[ih * 4 + 1]),
                                               cvt_tf32(gr[ih * 4 + 2]), cvt_tf32(gr[ih * 4 + 3]));
            }
            c00 = n00; c01 = n01; c10 = n10; c11 = n11;
        }
        // 4) stage boundary
        __syncthreads();
    }

    // ---- shuffle restage (d-frag -> A-frag permutation, validated R5/R7/R8/R9) ----
    const int srcA = (l & 28) | ((l & 3) >> 1);
    const int srcB = srcA + 2;
    const bool odd = (l & 1);

    #define RESTAGE(dd_, a_) do {                                                    \
        float x0 = __shfl_sync(0xffffffffu, (dd_)[0], srcA);                         \
        float x1 = __shfl_sync(0xffffffffu, (dd_)[1], srcA);                         \
        float x2 = __shfl_sync(0xffffffffu, (dd_)[2], srcA);                         \
        float x3 = __shfl_sync(0xffffffffu, (dd_)[3], srcA);                         \
        float y0 = __shfl_sync(0xffffffffu, (dd_)[0], srcB);                         \
        float y1 = __shfl_sync(0xffffffffu, (dd_)[1], srcB);                         \
        float y2 = __shfl_sync(0xffffffffu, (dd_)[2], srcB);                         \
        float y3 = __shfl_sync(0xffffffffu, (dd_)[3], srcB);                         \
        (a_)[0] = cvt_tf32(odd ? x1 : x0);                                           \
        (a_)[1] = cvt_tf32(odd ? x3 : x2);                                           \
        (a_)[2] = cvt_tf32(odd ? y1 : y0);                                           \
        (a_)[3] = cvt_tf32(odd ? y3 : y2);                                           \
    } while (0)

    // ---- GEMM2: H[16x64] = [D1 | noise2][16x24] * w1^T[24x64] ----
    float hh[8][4];
    #pragma unroll
    for (int j = 0; j < 8; ++j) { hh[j][0] = hh[j][1] = hh[j][2] = hh[j][3] = 0.f; }
    {
        uint32_t a[4];
        #pragma unroll
        for (int kt = 0; kt < 3; ++kt) {
            if (kt == 0)      RESTAGE(d0, a);
            else if (kt == 1) RESTAGE(d1, a);
            else {
                a[0] = cvt_tf32(m2a0); a[1] = cvt_tf32(m2a1);
                a[2] = cvt_tf32(m2a2); a[3] = cvt_tf32(m2a3);
            }
            #pragma unroll
            for (int j = 0; j < 8; ++j) {
                uint2 bf = *(const uint2*)(sW1f + (j * 3 + kt) * 64 + l * 2);
                mma_tf32(hh[j], a, bf.x, bf.y);
            }
        }
    }

    // bias + relu in registers
    {
        int c0 = 2 * (l & 3);
        #pragma unroll
        for (int j = 0; j < 8; ++j) {
            float ba = sB1f[8 * j + c0], bb2 = sB1f[8 * j + c0 + 1];
            hh[j][0] = fmaxf(hh[j][0] + ba, 0.f);
            hh[j][1] = fmaxf(hh[j][1] + bb2, 0.f);
            hh[j][2] = fmaxf(hh[j][2] + ba, 0.f);
            hh[j][3] = fmaxf(hh[j][3] + bb2, 0.f);
        }
    }

    // ---- GEMM3: OUT[16x8] = H[16x64] * w2^T[64x8] ----
    float o[4] = {0.f, 0.f, 0.f, 0.f};
    {
        uint32_t a[4];
        #pragma unroll
        for (int j = 0; j < 8; ++j) {
            RESTAGE(hh[j], a);
            uint2 bf = *(const uint2*)(sW2f + j * 64 + l * 2);
            mma_tf32(o, a, bf.x, bf.y);
        }
    }
    {
        int f0  = 2 * (l & 3);
        int b0i = l >> 2;
        o[0] += sB2f[f0];
        o[1] += sB2f[f0 + 1];
        o[2] += sB2f[f0];
        o[3] += sB2f[f0 + 1];
        // stage to sOf[row][px], row stride 17
        sOf[(b0i * 8 + f0) * 17 + wid]           = o[0];
        sOf[(b0i * 8 + f0 + 1) * 17 + wid]       = o[1];
        sOf[((b0i + 8) * 8 + f0) * 17 + wid]     = o[2];
        sOf[((b0i + 8) * 8 + f0 + 1) * 17 + wid] = o[3];
    }
    __syncthreads();

    // ---- coalesced output: out[bf][p0..p0+15] ----
    {
        int bf = tid >> 2;
        int c  = tid & 3;
        const float* rp = sOf + bf * 17 + c * 4;
        float4 v = make_float4(rp[0], rp[1], rp[2], rp[3]);
        *(float4*)(out + (size_t)bf * NPIXC + p0 + c * 4) = v;
    }
    #undef WLOAD
    #undef RESTAGE
}

extern "C" void kernel_launch(void* const* d_in, const int* in_sizes, int n_in,
                              void* d_out, int out_size)
{
    const float* y    = (const float*)d_in[0];
    const float* nz   = (const float*)d_in[1];
    const float* nz2  = (const float*)d_in[2];
    const float* wmap = (const float*)d_in[3];
    const float* w1   = (const float*)d_in[4];
    const float* b1   = (const float*)d_in[5];
    const float* w2   = (const float*)d_in[6];
    const float* b2   = (const float*)d_in[7];
    const int*   nidx = (const int*)d_in[8];
    float* out = (float*)d_out;

    cudaFuncSetAttribute(lr_kernel, cudaFuncAttributeMaxDynamicSharedMemorySize, SMEM_BYTES);
    lr_kernel<<<NPIXC / PXB, THREADS, SMEM_BYTES>>>(y, nz, nz2, wmap, w1, b1, w2, b2, nidx, out);
}

// round 11
// speedup vs baseline: 1.7765x; 1.1692x over previous
#include <cuda_runtime.h>
#include <cstdint>

#define NPIXC   16384
#define PXB     16
#define THREADS 512

// persistent scratch: feats transposed into A-fragment order, tf32, 16 MB
__device__ uint32_t g_featsT[NPIXC * 256];

// main-kernel smem word offsets
#define OFF_W1F  0                  // 1536
#define OFF_B1   1536               // 64
#define OFF_W2F  1600               // 512
#define OFF_B2   2112               // 8
#define OFF_O    2120               // 128*17 = 2176
#define SMEM_WORDS 4296
#define SMEM_BYTES (SMEM_WORDS * 4)   // 17184

// transpose-kernel smem: ts[w*33 + px], 256*33 words
#define TR_SMEM_WORDS (256 * 33)
#define TR_SMEM_BYTES (TR_SMEM_WORDS * 4)  // 33792

__device__ __forceinline__ uint32_t cvt_tf32(float x) {
    uint32_t r;
    asm("cvt.rna.tf32.f32 %0, %1;" : "=r"(r) : "f"(x));
    return r;
}

__device__ __forceinline__ void mma_tf32(float* d, const uint32_t* a, uint32_t b0, uint32_t b1) {
    asm("mma.sync.aligned.m16n8k8.row.col.f32.tf32.tf32.f32 "
        "{%0,%1,%2,%3}, {%4,%5,%6,%7}, {%8,%9}, {%0,%1,%2,%3};"
        : "+f"(d[0]), "+f"(d[1]), "+f"(d[2]), "+f"(d[3])
        : "r"(a[0]), "r"(a[1]), "r"(a[2]), "r"(a[3]), "r"(b0), "r"(b1));
}

// ---------------------------------------------------------------------------
// Kernel A: transpose feats [b][n][pix] -> featsT[pix][fragword], tf32
// fragword w for (b, n): t=n>>3, n7=n&7:
//   l = (b&7)*4 + (n7>>1); j = 2*(n7&1) + (b>>3); w = t*128 + l*4 + j
// ---------------------------------------------------------------------------
__global__ void __launch_bounds__(256)
tr_kernel(const float* __restrict__ y, const float* __restrict__ nz)
{
    extern __shared__ uint32_t ts[];
    const int tid  = threadIdx.x;
    const int lane = tid & 31;
    const int wid  = tid >> 5;
    const int p0   = blockIdx.x * 32;

    // read phase: warp wid handles 32 planes; lane = pixel (coalesced)
    #pragma unroll 4
    for (int i = 0; i < 32; ++i) {
        int pl = wid * 32 + i;          // 0..255
        int b  = pl >> 4;
        int n  = pl & 15;
        const float* src = (n < 8) ? (y  + (size_t)(b * 8 + n)     * NPIXC)
                                   : (nz + (size_t)(b * 8 + n - 8) * NPIXC);
        float v = __ldg(src + p0 + lane);
        int t  = n >> 3, n7 = n & 7;
        int w  = t * 128 + ((b & 7) * 4 + (n7 >> 1)) * 4 + 2 * (n7 & 1) + (b >> 3);
        ts[w * 33 + lane] = cvt_tf32(v);
    }
    __syncthreads();

    // write phase: coalesced STG.128 (4 px * 128B per warp-instr)
    const int px = tid >> 3;
    const int lo = (tid & 7) * 4;
    uint32_t* dst = g_featsT + (size_t)(p0 + px) * 256;
    #pragma unroll
    for (int sub = 0; sub < 8; ++sub) {
        int w = sub * 32 + lo;
        uint4 v = make_uint4(ts[(w + 0) * 33 + px], ts[(w + 1) * 33 + px],
                             ts[(w + 2) * 33 + px], ts[(w + 3) * 33 + px]);
        *(uint4*)(dst + w) = v;
    }
}

// ---------------------------------------------------------------------------
// Kernel B: barrier-free warp-per-pixel einsum + fused MLP
// ---------------------------------------------------------------------------
__global__ void __launch_bounds__(THREADS, 2)
lr_kernel(const float* __restrict__ nz2,   // [16][NPIX][8]
          const float* __restrict__ wmap,  // [NPIX][9][16][16]
          const float* __restrict__ w1,    // [64][24]
          const float* __restrict__ b1,    // [64]
          const float* __restrict__ w2,    // [8][64]
          const float* __restrict__ b2,    // [8]
          const int*   __restrict__ nidx,  // [NPIX][9]
          float*       __restrict__ out)   // [16][8][NPIX]
{
    extern __shared__ uint32_t su[];
    uint32_t* sW1f = su + OFF_W1F;
    float*    sB1f = (float*)(su + OFF_B1);
    uint32_t* sW2f = su + OFF_W2F;
    float*    sB2f = (float*)(su + OFF_B2);
    float*    sOf  = (float*)(su + OFF_O);

    const int tid = threadIdx.x;
    const int p0  = blockIdx.x * PXB;
    const int l   = tid & 31;
    const int wid = tid >> 5;               // warp id == pixel
    const int p   = p0 + wid;

    // ---- small shared weights (fragment-ordered) ----
    for (int i = tid; i < 1536; i += THREADS) {          // w1^T B-frags [j8][kt3][l32][rg2]
        int j = i / 192, r = i - j * 192;
        int kt = r >> 6, r2 = r & 63, ll = r2 >> 1, rg = r2 & 1;
        int d = kt * 8 + (ll & 3) + rg * 4;
        int ii = j * 8 + (ll >> 2);
        sW1f[i] = cvt_tf32(w1[ii * 24 + d]);
    }
    if (tid < 512) {                                     // w2^T B-frags [kt8][l32][rg2]
        int i = tid;
        int kt = i >> 6, r2 = i & 63, ll = r2 >> 1, rg = r2 & 1;
        int row = kt * 8 + (ll & 3) + 4 * rg;
        int col = ll >> 2;
        sW2f[i] = cvt_tf32(w2[col * 64 + row]);
    }
    if (tid < 64)  sB1f[tid] = b1[tid];
    if (tid < 8)   sB2f[tid] = b2[tid];

    // ---- early loads: noise2 A-fragment for GEMM2 kt=2 ----
    float m2a0 = __ldg(nz2 + ((size_t)(l >> 2) * NPIXC + p) * 8 + (l & 3));
    float m2a1 = __ldg(nz2 + ((size_t)((l >> 2) + 8) * NPIXC + p) * 8 + (l & 3));
    float m2a2 = __ldg(nz2 + ((size_t)(l >> 2) * NPIXC + p) * 8 + (l & 3) + 4);
    float m2a3 = __ldg(nz2 + ((size_t)((l >> 2) + 8) * NPIXC + p) * 8 + (l & 3) + 4);

    // ---- neighbor indices (lane-uniform, kept in registers) ----
    int q[9];
    #pragma unroll
    for (int k = 0; k < 9; ++k) q[k] = __ldg(nidx + p * 9 + k);

    // ---- einsum: warp-private, barrier-free, 1-slice register prefetch ----
    const float* wp = wmap + (size_t)p * 2304 + (l >> 2) * 16 + 2 * (l & 3);
    #define WLOAD(s_, r00, r01, r10, r11) do {                                       \
        const float* wt = wp + (s_) * 256;                                           \
        r00 = *(const float2*)(wt);                                                  \
        r01 = *(const float2*)(wt + 128);                                            \
        r10 = *(const float2*)(wt + 8);                                              \
        r11 = *(const float2*)(wt + 136);                                            \
    } while (0)

    float d0[4] = {0.f, 0.f, 0.f, 0.f};
    float d1[4] = {0.f, 0.f, 0.f, 0.f};

    uint4 a0c = __ldg((const uint4*)(g_featsT + (size_t)q[0] * 256 + l * 4));
    uint4 a1c = __ldg((const uint4*)(g_featsT + (size_t)q[0] * 256 + 128 + l * 4));
    float2 c00, c01, c10, c11;
    WLOAD(0, c00, c01, c10, c11);

    #pragma unroll
    for (int k = 0; k < 9; ++k) {
        uint4 a0n, a1n;
        float2 n00, n01, n10, n11;
        if (k < 8) {
            a0n = __ldg((const uint4*)(g_featsT + (size_t)q[k + 1] * 256 + l * 4));
            a1n = __ldg((const uint4*)(g_featsT + (size_t)q[k + 1] * 256 + 128 + l * 4));
            WLOAD(k + 1, n00, n01, n10, n11);
        }
        {
            uint32_t A0[4] = {a0c.x, a0c.y, a0c.z, a0c.w};
            mma_tf32(d0, A0, cvt_tf32(c00.x), cvt_tf32(c00.y));
            mma_tf32(d1, A0, cvt_tf32(c01.x), cvt_tf32(c01.y));
            uint32_t A1[4] = {a1c.x, a1c.y, a1c.z, a1c.w};
            mma_tf32(d0, A1, cvt_tf32(c10.x), cvt_tf32(c10.y));
            mma_tf32(d1, A1, cvt_tf32(c11.x), cvt_tf32(c11.y));
        }
        if (k < 8) {
            a0c = a0n; a1c = a1n;
            c00 = n00; c01 = n01; c10 = n10; c11 = n11;
        }
    }
    __syncthreads();   // sW1f/sW2f ready (filled above; einsum gave plenty of slack)

    // ---- shuffle restage (d-frag -> A-frag permutation, validated R5..R10) ----
    const int srcA = (l & 28) | ((l & 3) >> 1);
    const int srcB = srcA + 2;
    const bool odd = (l & 1);

    #define RESTAGE(dd_, a_) do {                                                    \
        float x0 = __shfl_sync(0xffffffffu, (dd_)[0], srcA);                         \
        float x1 = __shfl_sync(0xffffffffu, (dd_)[1], srcA);                         \
        float x2 = __shfl_sync(0xffffffffu, (dd_)[2], srcA);                         \
        float x3 = __shfl_sync(0xffffffffu, (dd_)[3], srcA);                         \
        float y0 = __shfl_sync(0xffffffffu, (dd_)[0], srcB);                         \
        float y1 = __shfl_sync(0xffffffffu, (dd_)[1], srcB);                         \
        float y2 = __shfl_sync(0xffffffffu, (dd_)[2], srcB);                         \
        float y3 = __shfl_sync(0xffffffffu, (dd_)[3], srcB);                         \
        (a_)[0] = cvt_tf32(odd ? x1 : x0);                                           \
        (a_)[1] = cvt_tf32(odd ? x3 : x2);                                           \
        (a_)[2] = cvt_tf32(odd ? y1 : y0);                                           \
        (a_)[3] = cvt_tf32(odd ? y3 : y2);                                           \
    } while (0)

    // ---- GEMM2: H[16x64] = [D1 | noise2][16x24] * w1^T[24x64] ----
    float hh[8][4];
    #pragma unroll
    for (int j = 0; j < 8; ++j) { hh[j][0] = hh[j][1] = hh[j][2] = hh[j][3] = 0.f; }
    {
        uint32_t a[4];
        #pragma unroll
        for (int kt = 0; kt < 3; ++kt) {
            if (kt == 0)      RESTAGE(d0, a);
            else if (kt == 1) RESTAGE(d1, a);
            else {
                a[0] = cvt_tf32(m2a0); a[1] = cvt_tf32(m2a1);
                a[2] = cvt_tf32(m2a2); a[3] = cvt_tf32(m2a3);
            }
            #pragma unroll
            for (int j = 0; j < 8; ++j) {
                uint2 bf = *(const uint2*)(sW1f + (j * 3 + kt) * 64 + l * 2);
                mma_tf32(hh[j], a, bf.x, bf.y);
            }
        }
    }

    // bias + relu in registers
    {
        int c0 = 2 * (l & 3);
        #pragma unroll
        for (int j = 0; j < 8; ++j) {
            float ba = sB1f[8 * j + c0], bb2 = sB1f[8 * j + c0 + 1];
            hh[j][0] = fmaxf(hh[j][0] + ba, 0.f);
            hh[j][1] = fmaxf(hh[j][1] + bb2, 0.f);
            hh[j][2] = fmaxf(hh[j][2] + ba, 0.f);
            hh[j][3] = fmaxf(hh[j][3] + bb2, 0.f);
        }
    }

    // ---- GEMM3: OUT[16x8] = H[16x64] * w2^T[64x8] ----
    float o[4] = {0.f, 0.f, 0.f, 0.f};
    {
        uint32_t a[4];
        #pragma unroll
        for (int j = 0; j < 8; ++j) {
            RESTAGE(hh[j], a);
            uint2 bf = *(const uint2*)(sW2f + j * 64 + l * 2);
            mma_tf32(o, a, bf.x, bf.y);
        }
    }
    {
        int f0  = 2 * (l & 3);
        int b0i = l >> 2;
        o[0] += sB2f[f0];
        o[1] += sB2f[f0 + 1];
        o[2] += sB2f[f0];
        o[3] += sB2f[f0 + 1];
        sOf[(b0i * 8 + f0) * 17 + wid]           = o[0];
        sOf[(b0i * 8 + f0 + 1) * 17 + wid]       = o[1];
        sOf[((b0i + 8) * 8 + f0) * 17 + wid]     = o[2];
        sOf[((b0i + 8) * 8 + f0 + 1) * 17 + wid] = o[3];
    }
    __syncthreads();

    // ---- coalesced output: out[bf][p0..p0+15] ----
    {
        int bf = tid >> 2;
        int c  = tid & 3;
        const float* rp = sOf + bf * 17 + c * 4;
        float4 v = make_float4(rp[0], rp[1], rp[2], rp[3]);
        *(float4*)(out + (size_t)bf * NPIXC + p0 + c * 4) = v;
    }
    #undef WLOAD
    #undef RESTAGE
}

extern "C" void kernel_launch(void* const* d_in, const int* in_sizes, int n_in,
                              void* d_out, int out_size)
{
    const float* y    = (const float*)d_in[0];
    const float* nz   = (const float*)d_in[1];
    const float* nz2  = (const float*)d_in[2];
    const float* wmap = (const float*)d_in[3];
    const float* w1   = (const float*)d_in[4];
    const float* b1   = (const float*)d_in[5];
    const float* w2   = (const float*)d_in[6];
    const float* b2   = (const float*)d_in[7];
    const int*   nidx = (const int*)d_in[8];
    float* out = (float*)d_out;

    cudaFuncSetAttribute(tr_kernel, cudaFuncAttributeMaxDynamicSharedMemorySize, TR_SMEM_BYTES);
    cudaFuncSetAttribute(lr_kernel, cudaFuncAttributeMaxDynamicSharedMemorySize, SMEM_BYTES);

    tr_kernel<<<NPIXC / 32, 256, TR_SMEM_BYTES>>>(y, nz);
    lr_kernel<<<NPIXC / PXB, THREADS, SMEM_BYTES>>>(nz2, wmap, w1, b1, w2, b2, nidx, out);
}